// round 1
// baseline (speedup 1.0000x reference)
#include <cuda_runtime.h>
#include <cuda_bf16.h>

// ---------------- problem constants (fixed by the reference) ----------------
// N=32768 nodes, M=8192 edges, D=128, H=128, NH=2 -> H*NH=256, HD=64
#define NMAX 32768
#define MMAX 8192
#define EMAX 49152               // <= M*K = 8192*6
#define TMAX 294912              // <= 36*M
#define PMAX (TMAX + NMAX)       // unique pairs + self-loop fill

// ---------------- scratch (device globals; allocation-free rule) ------------
__device__ float4 g_nodeS[NMAX * 64];   // node_feat @ Wsi          [N,256]
__device__ float4 g_nodeT[NMAX * 64];   // node_feat @ Wti          [N,256]
__device__ float4 g_nodeT2[NMAX * 64];  // node_feat @ Wte          [N,256]
__device__ float4 g_nodeM[NMAX * 32];   // node_feat @ Wmi_top      [N,128]
__device__ float4 g_edgeB[MMAX * 64];   // edge_feat @ Wbi          [M,256]
__device__ float4 g_edgeS[MMAX * 64];   // edge_feat @ Wse          [M,256]
__device__ float4 g_edgeM[MMAX * 32];   // edge_feat @ Wmi_bot      [M,128]
__device__ float4 g_edgeMe[MMAX * 32];  // edge_feat @ Wme          [M,128]
__device__ float4 g_accB[PMAX * 64];    // scatter of edgeB by pair [P,256]
__device__ float4 g_accM[PMAX * 32];    // scatter of edgeM by pair [P,128]
__device__ float4 g_accI[NMAX * 32];    // intra message accum      [N,128]
__device__ float4 g_accE[NMAX * 32];    // inter message accum      [N,128]
__device__ float  g_exI[PMAX * 2];
__device__ float  g_exE[EMAX * 2];
__device__ float  g_denomI[NMAX * 2];
__device__ float  g_denomE[NMAX * 2];

// ---------------- small helpers ----------------
__device__ __forceinline__ float4 f4add(float4 a, float4 b) {
    return make_float4(a.x + b.x, a.y + b.y, a.z + b.z, a.w + b.w);
}
__device__ __forceinline__ float4 f4fma(float4 a, float s, float4 b) {
    return make_float4(fmaf(a.x, s, b.x), fmaf(a.y, s, b.y), fmaf(a.z, s, b.z), fmaf(a.w, s, b.w));
}
__device__ __forceinline__ float4 f4muls(float4 a, float s) {
    return make_float4(a.x * s, a.y * s, a.z * s, a.w * s);
}
__device__ __forceinline__ float gelu_exact(float x) {
    return 0.5f * x * (1.0f + erff(x * 0.70710678118654752f));
}
__device__ __forceinline__ void red4(float* addr, float4 v) {
    asm volatile("red.global.add.v4.f32 [%0], {%1,%2,%3,%4};"
                 :: "l"(addr), "f"(v.x), "f"(v.y), "f"(v.z), "f"(v.w) : "memory");
}

// ---------------- zero scratch (atomically-accumulated buffers only) --------
__global__ void zero_scratch(long nB, long nM, long nNode, long nDen) {
    long i0 = (long)blockIdx.x * blockDim.x + threadIdx.x;
    long stride = (long)gridDim.x * blockDim.x;
    float4 z = make_float4(0.f, 0.f, 0.f, 0.f);
    for (long i = i0; i < nB; i += stride) g_accB[i] = z;
    for (long i = i0; i < nM; i += stride) g_accM[i] = z;
    for (long i = i0; i < nNode; i += stride) { g_accI[i] = z; g_accE[i] = z; }
    for (long i = i0; i < nDen; i += stride) {
        ((float4*)g_denomI)[i] = z;
        ((float4*)g_denomE)[i] = z;
    }
}

// ---------------- tiled fp32 GEMM: C[rows,CC] = A[rows,128] @ W[128,CC] -----
// rows % 128 == 0, CC % 64 == 0. Optional bias + accumulate.
__global__ void gemm_k128(const float* __restrict__ A, const float* __restrict__ W,
                          const float* __restrict__ bias, float* __restrict__ C,
                          int CC, int accumulate) {
    __shared__ float As[32][132];  // [k][row], padded
    __shared__ float Ws[32][68];   // [k][col], padded
    const int tid = threadIdx.x;
    const int tx = tid & 15;       // 16 cols groups * 4
    const int ty = tid >> 4;       // 16 row groups * 8
    const long r0 = (long)blockIdx.y * 128;
    const int  c0 = blockIdx.x * 64;

    float acc[8][4];
#pragma unroll
    for (int i = 0; i < 8; i++)
#pragma unroll
        for (int j = 0; j < 4; j++) acc[i][j] = 0.f;

    for (int kb = 0; kb < 128; kb += 32) {
        {   // load A tile 128x32, transpose into As[k][row]
            int row = tid >> 1;
            int k4 = (tid & 1) * 16;
            const float* ap = A + (r0 + row) * 128 + kb + k4;
#pragma unroll
            for (int q = 0; q < 4; q++) {
                float4 v = *(const float4*)(ap + q * 4);
                As[k4 + q * 4 + 0][row] = v.x;
                As[k4 + q * 4 + 1][row] = v.y;
                As[k4 + q * 4 + 2][row] = v.z;
                As[k4 + q * 4 + 3][row] = v.w;
            }
        }
        {   // load W tile 32x64
            int wrow = tid >> 3;
            int cq = (tid & 7) * 8;
            const float* wp = W + (long)(kb + wrow) * CC + c0 + cq;
            float4 v0 = *(const float4*)(wp);
            float4 v1 = *(const float4*)(wp + 4);
            *(float4*)&Ws[wrow][cq] = v0;
            *(float4*)&Ws[wrow][cq + 4] = v1;
        }
        __syncthreads();
#pragma unroll
        for (int k = 0; k < 32; k++) {
            float4 a0 = *(const float4*)&As[k][ty * 8];
            float4 a1 = *(const float4*)&As[k][ty * 8 + 4];
            float4 w = *(const float4*)&Ws[k][tx * 4];
            float ar[8] = {a0.x, a0.y, a0.z, a0.w, a1.x, a1.y, a1.z, a1.w};
            float wr[4] = {w.x, w.y, w.z, w.w};
#pragma unroll
            for (int i = 0; i < 8; i++)
#pragma unroll
                for (int j = 0; j < 4; j++) acc[i][j] = fmaf(ar[i], wr[j], acc[i][j]);
        }
        __syncthreads();
    }

    float4 b = bias ? *(const float4*)(bias + c0 + tx * 4) : make_float4(0.f, 0.f, 0.f, 0.f);
#pragma unroll
    for (int i = 0; i < 8; i++) {
        long r = r0 + ty * 8 + i;
        float* cp = C + r * CC + c0 + tx * 4;
        float4 v = make_float4(acc[i][0] + b.x, acc[i][1] + b.y, acc[i][2] + b.z, acc[i][3] + b.w);
        if (accumulate) {
            float4 o = *(const float4*)cp;
            v.x += o.x; v.y += o.y; v.z += o.z; v.w += o.w;
        }
        *(float4*)cp = v;
    }
}

// ---------------- triple scatter: accB[p] += edgeB[e]; accM[p] += edgeM[e] --
__global__ void scatter_triples(const int* __restrict__ tri_pair,
                                const int* __restrict__ tri_edge, int T) {
    int w = (int)(((long)blockIdx.x * blockDim.x + threadIdx.x) >> 5);
    int lane = threadIdx.x & 31;
    if (w >= T) return;
    int p = tri_pair[w];
    int e = tri_edge[w];
    float4 b0 = g_edgeB[(long)e * 64 + lane];
    float4 b1 = g_edgeB[(long)e * 64 + 32 + lane];
    float4 m  = g_edgeM[(long)e * 32 + lane];
    red4((float*)(g_accB + (long)p * 64 + lane), b0);
    red4((float*)(g_accB + (long)p * 64 + 32 + lane), b1);
    red4((float*)(g_accM + (long)p * 32 + lane), m);
}

// ---------------- intra attention logits + exp + denom (warp per pair) -----
__global__ void intra_logits(const int* __restrict__ pair_src, const int* __restrict__ pair_tgt,
                             const float* __restrict__ pair_cnt,
                             const float4* __restrict__ bsi, const float4* __restrict__ bti,
                             const float4* __restrict__ bbi, const float4* __restrict__ ai,
                             int P) {
    int w = (int)(((long)blockIdx.x * blockDim.x + threadIdx.x) >> 5);
    int lane = threadIdx.x & 31;
    if (w >= P) return;
    int s = pair_src[w], t = pair_tgt[w];
    float inv = 1.0f / pair_cnt[w];
    float4 b0 = f4add(f4add(bsi[lane], bti[lane]), bbi[lane]);
    float4 b1 = f4add(f4add(bsi[32 + lane], bti[32 + lane]), bbi[32 + lane]);
    long sb = (long)s * 64 + lane, tb = (long)t * 64 + lane, pb = (long)w * 64 + lane;
    float4 u0 = f4add(f4add(g_nodeS[sb], g_nodeT[tb]), f4fma(g_accB[pb], inv, b0));
    float4 u1 = f4add(f4add(g_nodeS[sb + 32], g_nodeT[tb + 32]), f4fma(g_accB[pb + 32], inv, b1));
    float4 a0 = ai[lane], a1 = ai[32 + lane];
    float l0 = gelu_exact(u0.x) * a0.x + gelu_exact(u0.y) * a0.y +
               gelu_exact(u0.z) * a0.z + gelu_exact(u0.w) * a0.w;
    float l1 = gelu_exact(u1.x) * a1.x + gelu_exact(u1.y) * a1.y +
               gelu_exact(u1.z) * a1.z + gelu_exact(u1.w) * a1.w;
#pragma unroll
    for (int off = 16; off; off >>= 1) {
        l0 += __shfl_down_sync(0xffffffffu, l0, off);
        l1 += __shfl_down_sync(0xffffffffu, l1, off);
    }
    if (lane == 0) {
        float e0 = expf(l0), e1 = expf(l1);
        g_exI[(long)w * 2] = e0;
        g_exI[(long)w * 2 + 1] = e1;
        atomicAdd(&g_denomI[t * 2], e0);
        atomicAdd(&g_denomI[t * 2 + 1], e1);
    }
}

// ---------------- intra message + softmax-scale + scatter (warp per pair) ---
__global__ void intra_msg(const int* __restrict__ pair_src, const int* __restrict__ pair_tgt,
                          const float* __restrict__ pair_cnt,
                          const float4* __restrict__ bmi, int P) {
    int w = (int)(((long)blockIdx.x * blockDim.x + threadIdx.x) >> 5);
    int lane = threadIdx.x & 31;
    if (w >= P) return;
    int s = pair_src[w], t = pair_tgt[w];
    float inv = 1.0f / pair_cnt[w];
    int h = lane >> 4;  // cols 0..63 -> head 0, 64..127 -> head 1
    float sc = g_exI[(long)w * 2 + h] / g_denomI[t * 2 + h];
    float4 m = f4add(g_nodeM[(long)s * 32 + lane],
                     f4fma(g_accM[(long)w * 32 + lane], inv, bmi[lane]));
    m = f4muls(m, sc);
    red4((float*)(g_accI + (long)t * 32 + lane), m);
}

// ---------------- inter attention logits (warp per incidence) ---------------
__global__ void inter_logits(const int* __restrict__ inc_edge, const int* __restrict__ inc_node,
                             const float4* __restrict__ bse, const float4* __restrict__ bte,
                             const float4* __restrict__ ae, int E) {
    int w = (int)(((long)blockIdx.x * blockDim.x + threadIdx.x) >> 5);
    int lane = threadIdx.x & 31;
    if (w >= E) return;
    int e = inc_edge[w], n = inc_node[w];
    float4 b0 = f4add(bse[lane], bte[lane]);
    float4 b1 = f4add(bse[32 + lane], bte[32 + lane]);
    long eb = (long)e * 64 + lane, nb = (long)n * 64 + lane;
    float4 u0 = f4add(f4add(g_edgeS[eb], g_nodeT2[nb]), b0);
    float4 u1 = f4add(f4add(g_edgeS[eb + 32], g_nodeT2[nb + 32]), b1);
    float4 a0 = ae[lane], a1 = ae[32 + lane];
    float l0 = gelu_exact(u0.x) * a0.x + gelu_exact(u0.y) * a0.y +
               gelu_exact(u0.z) * a0.z + gelu_exact(u0.w) * a0.w;
    float l1 = gelu_exact(u1.x) * a1.x + gelu_exact(u1.y) * a1.y +
               gelu_exact(u1.z) * a1.z + gelu_exact(u1.w) * a1.w;
#pragma unroll
    for (int off = 16; off; off >>= 1) {
        l0 += __shfl_down_sync(0xffffffffu, l0, off);
        l1 += __shfl_down_sync(0xffffffffu, l1, off);
    }
    if (lane == 0) {
        float e0 = expf(l0), e1 = expf(l1);
        g_exE[(long)w * 2] = e0;
        g_exE[(long)w * 2 + 1] = e1;
        atomicAdd(&g_denomE[n * 2], e0);
        atomicAdd(&g_denomE[n * 2 + 1], e1);
    }
}

// ---------------- inter message + scatter (warp per incidence) --------------
__global__ void inter_msg(const int* __restrict__ inc_edge, const int* __restrict__ inc_node,
                          const float4* __restrict__ bme, int E) {
    int w = (int)(((long)blockIdx.x * blockDim.x + threadIdx.x) >> 5);
    int lane = threadIdx.x & 31;
    if (w >= E) return;
    int e = inc_edge[w], n = inc_node[w];
    int h = lane >> 4;
    float sc = g_exE[(long)w * 2 + h] / g_denomE[n * 2 + h];
    float4 m = f4muls(f4add(g_edgeMe[(long)e * 32 + lane], bme[lane]), sc);
    red4((float*)(g_accE + (long)n * 32 + lane), m);
}

// ---------------- launch ----------------------------------------------------
extern "C" void kernel_launch(void* const* d_in, const int* in_sizes, int n_in,
                              void* d_out, int out_size) {
    const float* node_feat = (const float*)d_in[0];
    const float* edge_feat = (const float*)d_in[1];
    const int*   inc_node  = (const int*)d_in[2];
    const int*   inc_edge  = (const int*)d_in[3];
    const int*   pair_src  = (const int*)d_in[4];
    const int*   pair_tgt  = (const int*)d_in[5];
    const float* pair_cnt  = (const float*)d_in[6];
    const int*   tri_pair  = (const int*)d_in[7];
    const int*   tri_edge  = (const int*)d_in[8];
    const float* Wsi = (const float*)d_in[9];
    const float* bsi = (const float*)d_in[10];
    const float* Wti = (const float*)d_in[11];
    const float* bti = (const float*)d_in[12];
    const float* Wbi = (const float*)d_in[13];
    const float* bbi = (const float*)d_in[14];
    const float* ai  = (const float*)d_in[15];
    const float* Wmi = (const float*)d_in[16];
    const float* bmi = (const float*)d_in[17];
    const float* Woi = (const float*)d_in[18];
    const float* boi = (const float*)d_in[19];
    const float* Wse = (const float*)d_in[20];
    const float* bse = (const float*)d_in[21];
    const float* Wte = (const float*)d_in[22];
    const float* bte = (const float*)d_in[23];
    const float* ae  = (const float*)d_in[24];
    const float* Wme = (const float*)d_in[25];
    const float* bme = (const float*)d_in[26];
    const float* Woe = (const float*)d_in[27];
    const float* boe = (const float*)d_in[28];

    const int N = in_sizes[0] / 128;
    const int M = in_sizes[1] / 128;
    const int E = in_sizes[2];
    const int P = in_sizes[4];
    const int T = in_sizes[7];
    if (N > NMAX || M > MMAX || E > EMAX || P > PMAX || T > TMAX) return;

    float *pNodeS, *pNodeT, *pNodeT2, *pNodeM, *pEdgeB, *pEdgeS, *pEdgeM, *pEdgeMe, *pAccI, *pAccE;
    cudaGetSymbolAddress((void**)&pNodeS, g_nodeS);
    cudaGetSymbolAddress((void**)&pNodeT, g_nodeT);
    cudaGetSymbolAddress((void**)&pNodeT2, g_nodeT2);
    cudaGetSymbolAddress((void**)&pNodeM, g_nodeM);
    cudaGetSymbolAddress((void**)&pEdgeB, g_edgeB);
    cudaGetSymbolAddress((void**)&pEdgeS, g_edgeS);
    cudaGetSymbolAddress((void**)&pEdgeM, g_edgeM);
    cudaGetSymbolAddress((void**)&pEdgeMe, g_edgeMe);
    cudaGetSymbolAddress((void**)&pAccI, g_accI);
    cudaGetSymbolAddress((void**)&pAccE, g_accE);

    float* out = (float*)d_out;

    // 1) zero atomically-accumulated scratch
    zero_scratch<<<32768, 256>>>((long)P * 64, (long)P * 32, (long)N * 32, (long)N / 2);

    // 2) node / edge projection GEMMs (K = 128)
    gemm_k128<<<dim3(4, N / 128), 256>>>(node_feat, Wsi, nullptr, pNodeS, 256, 0);
    gemm_k128<<<dim3(4, N / 128), 256>>>(node_feat, Wti, nullptr, pNodeT, 256, 0);
    gemm_k128<<<dim3(4, N / 128), 256>>>(node_feat, Wte, nullptr, pNodeT2, 256, 0);
    gemm_k128<<<dim3(2, N / 128), 256>>>(node_feat, Wmi, nullptr, pNodeM, 128, 0);          // Wmi top half
    gemm_k128<<<dim3(4, M / 128), 256>>>(edge_feat, Wbi, nullptr, pEdgeB, 256, 0);
    gemm_k128<<<dim3(4, M / 128), 256>>>(edge_feat, Wse, nullptr, pEdgeS, 256, 0);
    gemm_k128<<<dim3(2, M / 128), 256>>>(edge_feat, Wmi + 128 * 128, nullptr, pEdgeM, 128, 0); // Wmi bottom half
    gemm_k128<<<dim3(2, M / 128), 256>>>(edge_feat, Wme, nullptr, pEdgeMe, 128, 0);

    // 3) scatter projected edge features onto pairs (bridge, pre-projected)
    scatter_triples<<<(int)(((long)T * 32 + 255) / 256), 256>>>(tri_pair, tri_edge, T);

    // 4) intra-rank attention
    int pb = (int)(((long)P * 32 + 255) / 256);
    intra_logits<<<pb, 256>>>(pair_src, pair_tgt, pair_cnt,
                              (const float4*)bsi, (const float4*)bti, (const float4*)bbi,
                              (const float4*)ai, P);
    intra_msg<<<pb, 256>>>(pair_src, pair_tgt, pair_cnt, (const float4*)bmi, P);

    // 5) inter-rank attention
    int eb = (int)(((long)E * 32 + 255) / 256);
    inter_logits<<<eb, 256>>>(inc_edge, inc_node,
                              (const float4*)bse, (const float4*)bte, (const float4*)ae, E);
    inter_msg<<<eb, 256>>>(inc_edge, inc_node, (const float4*)bme, E);

    // 6) output projections: out = accI @ Woi + boi + accE @ Woe + boe
    gemm_k128<<<dim3(2, N / 128), 256>>>(pAccI, Woi, boi, out, 128, 0);
    gemm_k128<<<dim3(2, N / 128), 256>>>(pAccE, Woe, boe, out, 128, 1);
}

// round 2
// speedup vs baseline: 1.2931x; 1.2931x over previous
#include <cuda_runtime.h>
#include <cuda_bf16.h>

// ---------------- problem constants (fixed by the reference) ----------------
// N=32768 nodes, M=8192 edges, D=128, H=128, NH=2 -> H*NH=256, HD=64
#define NMAX 32768
#define MMAX 8192
#define EMAX 49152               // <= M*K = 8192*6
#define TMAX 294912              // <= 36*M
#define PMAX (TMAX + NMAX)       // unique pairs + self-loop fill

// ---------------- scratch (device globals; allocation-free rule) ------------
__device__ float4 g_nodeS[NMAX * 64];   // node_feat @ Wsi          [N,256]
__device__ float4 g_nodeT[NMAX * 64];   // node_feat @ Wti          [N,256]
__device__ float4 g_nodeT2[NMAX * 64];  // node_feat @ Wte          [N,256]
__device__ float4 g_nodeM[NMAX * 32];   // node_feat @ Wmi_top      [N,128]
__device__ float4 g_edgeB[MMAX * 64];   // edge_feat @ Wbi          [M,256]
__device__ float4 g_edgeS[MMAX * 64];   // edge_feat @ Wse          [M,256]
__device__ float4 g_edgeM[MMAX * 32];   // edge_feat @ Wmi_bot      [M,128]
__device__ float4 g_edgeMe[MMAX * 32];  // edge_feat @ Wme          [M,128]
__device__ float4 g_accB[PMAX * 64];    // scatter of edgeB by pair [P,256]
__device__ float4 g_accM[PMAX * 32];    // scatter of edgeM by pair [P,128]
__device__ float4 g_accI[NMAX * 32];    // intra message accum      [N,128]
__device__ float4 g_accE[NMAX * 32];    // inter message accum      [N,128]
__device__ float  g_exI[PMAX * 2];
__device__ float  g_exE[EMAX * 2];
__device__ float  g_denomI[NMAX * 2];
__device__ float  g_denomE[NMAX * 2];

// ---------------- small helpers ----------------
__device__ __forceinline__ float4 f4add(float4 a, float4 b) {
    return make_float4(a.x + b.x, a.y + b.y, a.z + b.z, a.w + b.w);
}
__device__ __forceinline__ float4 f4fma(float4 a, float s, float4 b) {
    return make_float4(fmaf(a.x, s, b.x), fmaf(a.y, s, b.y), fmaf(a.z, s, b.z), fmaf(a.w, s, b.w));
}
__device__ __forceinline__ float4 f4muls(float4 a, float s) {
    return make_float4(a.x * s, a.y * s, a.z * s, a.w * s);
}
__device__ __forceinline__ float gelu_exact(float x) {
    return 0.5f * x * (1.0f + erff(x * 0.70710678118654752f));
}
__device__ __forceinline__ void red4(float* addr, float4 v) {
    asm volatile("red.global.add.v4.f32 [%0], {%1,%2,%3,%4};"
                 :: "l"(addr), "f"(v.x), "f"(v.y), "f"(v.z), "f"(v.w) : "memory");
}
__device__ __forceinline__ unsigned f2tf32(float x) {
    unsigned r;
    asm("cvt.rna.tf32.f32 %0, %1;" : "=r"(r) : "f"(x));
    return r;
}

// ---------------- tf32 tensor-core GEMM -------------------------------------
// C[rows,CC] = A[rows,128] @ W[128,CC] (+bias) (+=C). rows%128==0, CC%64==0.
// Block tile 128x64, 8 warps (4 M x 2 N), warp tile 32x32 via m16n8k8 tf32.
#define AS_PITCH 132   // 132 % 32 == 4  -> A-frag LDS conflict-free
#define WS_PITCH 72    // 72 % 32 == 8   -> B-frag LDS conflict-free
#define GEMM_SMEM ((128 * AS_PITCH + 128 * WS_PITCH) * 4)

__global__ void gemm_tf32(const float* __restrict__ A, const float* __restrict__ W,
                          const float* __restrict__ bias, float* __restrict__ C,
                          int CC, int accumulate) {
    extern __shared__ unsigned sh[];
    unsigned* As = sh;                        // [128][AS_PITCH]
    unsigned* Ws = sh + 128 * AS_PITCH;       // [128][WS_PITCH]
    const int tid = threadIdx.x;
    const int lane = tid & 31;
    const int warp = tid >> 5;
    const int wm = warp & 3;                  // 4 warps along M (32 rows each)
    const int wn = warp >> 2;                 // 2 warps along N (32 cols each)
    const long r0 = (long)blockIdx.y * 128;
    const int  c0 = blockIdx.x * 64;

    // --- stage A tile [128][128] -> smem (tf32) ---
    {
        const float4* ap = (const float4*)(A + r0 * 128);
#pragma unroll
        for (int i = 0; i < 16; i++) {
            int idx = tid + i * 256;          // float4 index over [128][32]
            int row = idx >> 5;
            int c4 = idx & 31;
            float4 v = ap[idx];
            unsigned* dst = As + row * AS_PITCH + c4 * 4;
            dst[0] = f2tf32(v.x); dst[1] = f2tf32(v.y);
            dst[2] = f2tf32(v.z); dst[3] = f2tf32(v.w);
        }
    }
    // --- stage W tile [128][64] -> smem (tf32) ---
    {
#pragma unroll
        for (int i = 0; i < 8; i++) {
            int idx = tid + i * 256;          // float4 index over [128][16]
            int row = idx >> 4;
            int c4 = idx & 15;
            float4 v = *(const float4*)(W + (long)row * CC + c0 + c4 * 4);
            unsigned* dst = Ws + row * WS_PITCH + c4 * 4;
            dst[0] = f2tf32(v.x); dst[1] = f2tf32(v.y);
            dst[2] = f2tf32(v.z); dst[3] = f2tf32(v.w);
        }
    }
    __syncthreads();

    const int gid = lane >> 2;                // 0..7
    const int tig = lane & 3;                 // 0..3
    float c[2][4][4];
#pragma unroll
    for (int mt = 0; mt < 2; mt++)
#pragma unroll
        for (int nt = 0; nt < 4; nt++)
#pragma unroll
            for (int q = 0; q < 4; q++) c[mt][nt][q] = 0.f;

    const int arow = wm * 32 + gid;
    const int bcol = wn * 32 + gid;

#pragma unroll
    for (int k0 = 0; k0 < 128; k0 += 8) {
        unsigned a[2][4], b[4][2];
#pragma unroll
        for (int mt = 0; mt < 2; mt++) {
            const unsigned* ap = As + (arow + mt * 16) * AS_PITCH + k0 + tig;
            a[mt][0] = ap[0];                  // (gid,    tig)
            a[mt][1] = ap[8 * AS_PITCH];       // (gid+8,  tig)
            a[mt][2] = ap[4];                  // (gid,    tig+4)
            a[mt][3] = ap[8 * AS_PITCH + 4];   // (gid+8,  tig+4)
        }
#pragma unroll
        for (int nt = 0; nt < 4; nt++) {
            const unsigned* bp = Ws + (k0 + tig) * WS_PITCH + bcol + nt * 8 - gid + gid; // keep form
            // b0: (k=tig, col=gid), b1: (k=tig+4, col=gid)
            b[nt][0] = Ws[(k0 + tig) * WS_PITCH + bcol + nt * 8];
            b[nt][1] = Ws[(k0 + tig + 4) * WS_PITCH + bcol + nt * 8];
            (void)bp;
        }
#pragma unroll
        for (int mt = 0; mt < 2; mt++)
#pragma unroll
            for (int nt = 0; nt < 4; nt++)
                asm volatile(
                    "mma.sync.aligned.m16n8k8.row.col.f32.tf32.tf32.f32 "
                    "{%0,%1,%2,%3}, {%4,%5,%6,%7}, {%8,%9}, {%0,%1,%2,%3};"
                    : "+f"(c[mt][nt][0]), "+f"(c[mt][nt][1]),
                      "+f"(c[mt][nt][2]), "+f"(c[mt][nt][3])
                    : "r"(a[mt][0]), "r"(a[mt][1]), "r"(a[mt][2]), "r"(a[mt][3]),
                      "r"(b[nt][0]), "r"(b[nt][1]));
    }

    // --- epilogue ---
#pragma unroll
    for (int mt = 0; mt < 2; mt++) {
        long r = r0 + wm * 32 + mt * 16 + gid;
#pragma unroll
        for (int nt = 0; nt < 4; nt++) {
            int col = c0 + wn * 32 + nt * 8 + 2 * tig;
            float2 bv = bias ? *(const float2*)(bias + col) : make_float2(0.f, 0.f);
            float2 v0 = make_float2(c[mt][nt][0] + bv.x, c[mt][nt][1] + bv.y);
            float2 v1 = make_float2(c[mt][nt][2] + bv.x, c[mt][nt][3] + bv.y);
            float* p0 = C + r * CC + col;
            float* p1 = C + (r + 8) * CC + col;
            if (accumulate) {
                float2 o0 = *(const float2*)p0;
                float2 o1 = *(const float2*)p1;
                v0.x += o0.x; v0.y += o0.y;
                v1.x += o1.x; v1.y += o1.y;
            }
            *(float2*)p0 = v0;
            *(float2*)p1 = v1;
        }
    }
}

// ---------------- triple scatter: accB[p] += edgeB[e]; accM[p] += edgeM[e] --
__global__ void scatter_triples(const int* __restrict__ tri_pair,
                                const int* __restrict__ tri_edge, int T) {
    int w = (int)(((long)blockIdx.x * blockDim.x + threadIdx.x) >> 5);
    int lane = threadIdx.x & 31;
    if (w >= T) return;
    int p = tri_pair[w];
    int e = tri_edge[w];
    float4 b0 = g_edgeB[(long)e * 64 + lane];
    float4 b1 = g_edgeB[(long)e * 64 + 32 + lane];
    float4 m  = g_edgeM[(long)e * 32 + lane];
    red4((float*)(g_accB + (long)p * 64 + lane), b0);
    red4((float*)(g_accB + (long)p * 64 + 32 + lane), b1);
    red4((float*)(g_accM + (long)p * 32 + lane), m);
}

// ---------------- intra attention logits + exp + denom (warp per pair) -----
__global__ void intra_logits(const int* __restrict__ pair_src, const int* __restrict__ pair_tgt,
                             const float* __restrict__ pair_cnt,
                             const float4* __restrict__ bsi, const float4* __restrict__ bti,
                             const float4* __restrict__ bbi, const float4* __restrict__ ai,
                             int P) {
    int w = (int)(((long)blockIdx.x * blockDim.x + threadIdx.x) >> 5);
    int lane = threadIdx.x & 31;
    if (w >= P) return;
    int s = pair_src[w], t = pair_tgt[w];
    float inv = 1.0f / pair_cnt[w];
    float4 b0 = f4add(f4add(bsi[lane], bti[lane]), bbi[lane]);
    float4 b1 = f4add(f4add(bsi[32 + lane], bti[32 + lane]), bbi[32 + lane]);
    long sb = (long)s * 64 + lane, tb = (long)t * 64 + lane, pb = (long)w * 64 + lane;
    float4 u0 = f4add(f4add(g_nodeS[sb], g_nodeT[tb]), f4fma(g_accB[pb], inv, b0));
    float4 u1 = f4add(f4add(g_nodeS[sb + 32], g_nodeT[tb + 32]), f4fma(g_accB[pb + 32], inv, b1));
    float4 a0 = ai[lane], a1 = ai[32 + lane];
    float l0 = gelu_exact(u0.x) * a0.x + gelu_exact(u0.y) * a0.y +
               gelu_exact(u0.z) * a0.z + gelu_exact(u0.w) * a0.w;
    float l1 = gelu_exact(u1.x) * a1.x + gelu_exact(u1.y) * a1.y +
               gelu_exact(u1.z) * a1.z + gelu_exact(u1.w) * a1.w;
#pragma unroll
    for (int off = 16; off; off >>= 1) {
        l0 += __shfl_down_sync(0xffffffffu, l0, off);
        l1 += __shfl_down_sync(0xffffffffu, l1, off);
    }
    if (lane == 0) {
        float e0 = expf(l0), e1 = expf(l1);
        g_exI[(long)w * 2] = e0;
        g_exI[(long)w * 2 + 1] = e1;
        atomicAdd(&g_denomI[t * 2], e0);
        atomicAdd(&g_denomI[t * 2 + 1], e1);
    }
}

// ---------------- intra message + softmax-scale + scatter (warp per pair) ---
__global__ void intra_msg(const int* __restrict__ pair_src, const int* __restrict__ pair_tgt,
                          const float* __restrict__ pair_cnt,
                          const float4* __restrict__ bmi, int P) {
    int w = (int)(((long)blockIdx.x * blockDim.x + threadIdx.x) >> 5);
    int lane = threadIdx.x & 31;
    if (w >= P) return;
    int s = pair_src[w], t = pair_tgt[w];
    float inv = 1.0f / pair_cnt[w];
    int h = lane >> 4;  // cols 0..63 -> head 0, 64..127 -> head 1
    float sc = g_exI[(long)w * 2 + h] / g_denomI[t * 2 + h];
    float4 m = f4add(g_nodeM[(long)s * 32 + lane],
                     f4fma(g_accM[(long)w * 32 + lane], inv, bmi[lane]));
    m = f4muls(m, sc);
    red4((float*)(g_accI + (long)t * 32 + lane), m);
}

// ---------------- inter attention logits (warp per incidence) ---------------
__global__ void inter_logits(const int* __restrict__ inc_edge, const int* __restrict__ inc_node,
                             const float4* __restrict__ bse, const float4* __restrict__ bte,
                             const float4* __restrict__ ae, int E) {
    int w = (int)(((long)blockIdx.x * blockDim.x + threadIdx.x) >> 5);
    int lane = threadIdx.x & 31;
    if (w >= E) return;
    int e = inc_edge[w], n = inc_node[w];
    float4 b0 = f4add(bse[lane], bte[lane]);
    float4 b1 = f4add(bse[32 + lane], bte[32 + lane]);
    long eb = (long)e * 64 + lane, nb = (long)n * 64 + lane;
    float4 u0 = f4add(f4add(g_edgeS[eb], g_nodeT2[nb]), b0);
    float4 u1 = f4add(f4add(g_edgeS[eb + 32], g_nodeT2[nb + 32]), b1);
    float4 a0 = ae[lane], a1 = ae[32 + lane];
    float l0 = gelu_exact(u0.x) * a0.x + gelu_exact(u0.y) * a0.y +
               gelu_exact(u0.z) * a0.z + gelu_exact(u0.w) * a0.w;
    float l1 = gelu_exact(u1.x) * a1.x + gelu_exact(u1.y) * a1.y +
               gelu_exact(u1.z) * a1.z + gelu_exact(u1.w) * a1.w;
#pragma unroll
    for (int off = 16; off; off >>= 1) {
        l0 += __shfl_down_sync(0xffffffffu, l0, off);
        l1 += __shfl_down_sync(0xffffffffu, l1, off);
    }
    if (lane == 0) {
        float e0 = expf(l0), e1 = expf(l1);
        g_exE[(long)w * 2] = e0;
        g_exE[(long)w * 2 + 1] = e1;
        atomicAdd(&g_denomE[n * 2], e0);
        atomicAdd(&g_denomE[n * 2 + 1], e1);
    }
}

// ---------------- inter message + scatter (warp per incidence) --------------
__global__ void inter_msg(const int* __restrict__ inc_edge, const int* __restrict__ inc_node,
                          const float4* __restrict__ bme, int E) {
    int w = (int)(((long)blockIdx.x * blockDim.x + threadIdx.x) >> 5);
    int lane = threadIdx.x & 31;
    if (w >= E) return;
    int e = inc_edge[w], n = inc_node[w];
    int h = lane >> 4;
    float sc = g_exE[(long)w * 2 + h] / g_denomE[n * 2 + h];
    float4 m = f4muls(f4add(g_edgeMe[(long)e * 32 + lane], bme[lane]), sc);
    red4((float*)(g_accE + (long)n * 32 + lane), m);
}

// ---------------- launch ----------------------------------------------------
extern "C" void kernel_launch(void* const* d_in, const int* in_sizes, int n_in,
                              void* d_out, int out_size) {
    const float* node_feat = (const float*)d_in[0];
    const float* edge_feat = (const float*)d_in[1];
    const int*   inc_node  = (const int*)d_in[2];
    const int*   inc_edge  = (const int*)d_in[3];
    const int*   pair_src  = (const int*)d_in[4];
    const int*   pair_tgt  = (const int*)d_in[5];
    const float* pair_cnt  = (const float*)d_in[6];
    const int*   tri_pair  = (const int*)d_in[7];
    const int*   tri_edge  = (const int*)d_in[8];
    const float* Wsi = (const float*)d_in[9];
    const float* bsi = (const float*)d_in[10];
    const float* Wti = (const float*)d_in[11];
    const float* bti = (const float*)d_in[12];
    const float* Wbi = (const float*)d_in[13];
    const float* bbi = (const float*)d_in[14];
    const float* ai  = (const float*)d_in[15];
    const float* Wmi = (const float*)d_in[16];
    const float* bmi = (const float*)d_in[17];
    const float* Woi = (const float*)d_in[18];
    const float* boi = (const float*)d_in[19];
    const float* Wse = (const float*)d_in[20];
    const float* bse = (const float*)d_in[21];
    const float* Wte = (const float*)d_in[22];
    const float* bte = (const float*)d_in[23];
    const float* ae  = (const float*)d_in[24];
    const float* Wme = (const float*)d_in[25];
    const float* bme = (const float*)d_in[26];
    const float* Woe = (const float*)d_in[27];
    const float* boe = (const float*)d_in[28];

    const int N = in_sizes[0] / 128;
    const int M = in_sizes[1] / 128;
    const int E = in_sizes[2];
    const int P = in_sizes[4];
    const int T = in_sizes[7];
    if (N > NMAX || M > MMAX || E > EMAX || P > PMAX || T > TMAX) return;

    float *pNodeS, *pNodeT, *pNodeT2, *pNodeM, *pEdgeB, *pEdgeS, *pEdgeM, *pEdgeMe;
    float *pAccB, *pAccM, *pAccI, *pAccE, *pDenI, *pDenE;
    cudaGetSymbolAddress((void**)&pNodeS, g_nodeS);
    cudaGetSymbolAddress((void**)&pNodeT, g_nodeT);
    cudaGetSymbolAddress((void**)&pNodeT2, g_nodeT2);
    cudaGetSymbolAddress((void**)&pNodeM, g_nodeM);
    cudaGetSymbolAddress((void**)&pEdgeB, g_edgeB);
    cudaGetSymbolAddress((void**)&pEdgeS, g_edgeS);
    cudaGetSymbolAddress((void**)&pEdgeM, g_edgeM);
    cudaGetSymbolAddress((void**)&pEdgeMe, g_edgeMe);
    cudaGetSymbolAddress((void**)&pAccB, g_accB);
    cudaGetSymbolAddress((void**)&pAccM, g_accM);
    cudaGetSymbolAddress((void**)&pAccI, g_accI);
    cudaGetSymbolAddress((void**)&pAccE, g_accE);
    cudaGetSymbolAddress((void**)&pDenI, g_denomI);
    cudaGetSymbolAddress((void**)&pDenE, g_denomE);

    static bool attr_done = false;
    // cudaFuncSetAttribute is idempotent and cheap; call every time (no caching of work).
    cudaFuncSetAttribute(gemm_tf32, cudaFuncAttributeMaxDynamicSharedMemorySize, GEMM_SMEM);
    (void)attr_done;

    float* out = (float*)d_out;

    // 1) zero atomically-accumulated scratch (memset nodes)
    cudaMemsetAsync(pAccB, 0, (size_t)P * 256 * sizeof(float), 0);
    cudaMemsetAsync(pAccM, 0, (size_t)P * 128 * sizeof(float), 0);
    cudaMemsetAsync(pAccI, 0, (size_t)N * 128 * sizeof(float), 0);
    cudaMemsetAsync(pAccE, 0, (size_t)N * 128 * sizeof(float), 0);
    cudaMemsetAsync(pDenI, 0, (size_t)N * 2 * sizeof(float), 0);
    cudaMemsetAsync(pDenE, 0, (size_t)N * 2 * sizeof(float), 0);

    // 2) node / edge projection GEMMs (tf32 tensor cores, K = 128)
    gemm_tf32<<<dim3(4, N / 128), 256, GEMM_SMEM>>>(node_feat, Wsi, nullptr, pNodeS, 256, 0);
    gemm_tf32<<<dim3(4, N / 128), 256, GEMM_SMEM>>>(node_feat, Wti, nullptr, pNodeT, 256, 0);
    gemm_tf32<<<dim3(4, N / 128), 256, GEMM_SMEM>>>(node_feat, Wte, nullptr, pNodeT2, 256, 0);
    gemm_tf32<<<dim3(2, N / 128), 256, GEMM_SMEM>>>(node_feat, Wmi, nullptr, pNodeM, 128, 0);
    gemm_tf32<<<dim3(4, M / 128), 256, GEMM_SMEM>>>(edge_feat, Wbi, nullptr, pEdgeB, 256, 0);
    gemm_tf32<<<dim3(4, M / 128), 256, GEMM_SMEM>>>(edge_feat, Wse, nullptr, pEdgeS, 256, 0);
    gemm_tf32<<<dim3(2, M / 128), 256, GEMM_SMEM>>>(edge_feat, Wmi + 128 * 128, nullptr, pEdgeM, 128, 0);
    gemm_tf32<<<dim3(2, M / 128), 256, GEMM_SMEM>>>(edge_feat, Wme, nullptr, pEdgeMe, 128, 0);

    // 3) scatter projected edge features onto pairs (bridge, pre-projected)
    scatter_triples<<<(int)(((long)T * 32 + 255) / 256), 256>>>(tri_pair, tri_edge, T);

    // 4) intra-rank attention
    int pb = (int)(((long)P * 32 + 255) / 256);
    intra_logits<<<pb, 256>>>(pair_src, pair_tgt, pair_cnt,
                              (const float4*)bsi, (const float4*)bti, (const float4*)bbi,
                              (const float4*)ai, P);
    intra_msg<<<pb, 256>>>(pair_src, pair_tgt, pair_cnt, (const float4*)bmi, P);

    // 5) inter-rank attention
    int eb = (int)(((long)E * 32 + 255) / 256);
    inter_logits<<<eb, 256>>>(inc_edge, inc_node,
                              (const float4*)bse, (const float4*)bte, (const float4*)ae, E);
    inter_msg<<<eb, 256>>>(inc_edge, inc_node, (const float4*)bme, E);

    // 6) output projections: out = accI @ Woi + boi + accE @ Woe + boe
    gemm_tf32<<<dim3(2, N / 128), 256, GEMM_SMEM>>>(pAccI, Woi, boi, out, 128, 0);
    gemm_tf32<<<dim3(2, N / 128), 256, GEMM_SMEM>>>(pAccE, Woe, boe, out, 128, 1);
}

// round 3
// speedup vs baseline: 1.8388x; 1.4220x over previous
#include <cuda_runtime.h>
#include <cuda_bf16.h>

// ---------------- problem constants (fixed by the reference) ----------------
// N=32768 nodes, M=8192 edges, D=128, H=128, NH=2 -> H*NH=256, HD=64
#define NMAX 32768
#define MMAX 8192
#define EMAX 49152               // <= M*K = 8192*6
#define TMAX 294912              // <= 36*M
#define PMAX (TMAX + NMAX)       // unique pairs + self-loop fill

// ---------------- scratch (device globals; allocation-free rule) ------------
__device__ float4 g_nodeS[NMAX * 64];   // node_feat @ Wsi          [N,256]
__device__ float4 g_nodeT[NMAX * 64];   // node_feat @ Wti          [N,256]
__device__ float4 g_nodeT2[NMAX * 64];  // node_feat @ Wte          [N,256]
__device__ float4 g_nodeM[NMAX * 32];   // node_feat @ Wmi_top      [N,128]
__device__ float4 g_edgeB[MMAX * 64];   // edge_feat @ Wbi          [M,256]
__device__ float4 g_edgeS[MMAX * 64];   // edge_feat @ Wse          [M,256]
__device__ float4 g_edgeM[MMAX * 32];   // edge_feat @ Wmi_bot      [M,128]
__device__ float4 g_edgeMe[MMAX * 32];  // edge_feat @ Wme          [M,128]
__device__ float4 g_accI[NMAX * 32];    // intra message accum      [N,128]
__device__ float4 g_accE[NMAX * 32];    // inter message accum      [N,128]
__device__ float  g_exI[PMAX * 2];
__device__ float  g_exE[EMAX * 2];
__device__ float  g_denomI[NMAX * 2];
__device__ float  g_denomE[NMAX * 2];
// CSR: pair -> bridging edges
__device__ int    g_cnt[PMAX];          // deg per pair
__device__ int    g_off[PMAX];          // exclusive offsets
__device__ int    g_head[PMAX];         // fill cursors
__device__ int    g_csr[TMAX];          // edge ids grouped by pair
__device__ int    g_partial[1024];      // scan block partials

// ---------------- small helpers ----------------
__device__ __forceinline__ float4 f4add(float4 a, float4 b) {
    return make_float4(a.x + b.x, a.y + b.y, a.z + b.z, a.w + b.w);
}
__device__ __forceinline__ float4 f4fma(float4 a, float s, float4 b) {
    return make_float4(fmaf(a.x, s, b.x), fmaf(a.y, s, b.y), fmaf(a.z, s, b.z), fmaf(a.w, s, b.w));
}
__device__ __forceinline__ float4 f4muls(float4 a, float s) {
    return make_float4(a.x * s, a.y * s, a.z * s, a.w * s);
}
__device__ __forceinline__ float gelu_exact(float x) {
    return 0.5f * x * (1.0f + erff(x * 0.70710678118654752f));
}
__device__ __forceinline__ void red4(float* addr, float4 v) {
    asm volatile("red.global.add.v4.f32 [%0], {%1,%2,%3,%4};"
                 :: "l"(addr), "f"(v.x), "f"(v.y), "f"(v.z), "f"(v.w) : "memory");
}
__device__ __forceinline__ unsigned f2tf32(float x) {
    unsigned r;
    asm("cvt.rna.tf32.f32 %0, %1;" : "=r"(r) : "f"(x));
    return r;
}

// ---------------- tf32 tensor-core GEMM -------------------------------------
// C[rows,CC] = A[rows,128] @ W[128,CC] (+bias) (+=C). rows%128==0, CC%64==0.
#define AS_PITCH 132
#define WS_PITCH 72
#define GEMM_SMEM ((128 * AS_PITCH + 128 * WS_PITCH) * 4)

__global__ void gemm_tf32(const float* __restrict__ A, const float* __restrict__ W,
                          const float* __restrict__ bias, float* __restrict__ C,
                          int CC, int accumulate) {
    extern __shared__ unsigned sh[];
    unsigned* As = sh;                        // [128][AS_PITCH]
    unsigned* Ws = sh + 128 * AS_PITCH;       // [128][WS_PITCH]
    const int tid = threadIdx.x;
    const int lane = tid & 31;
    const int warp = tid >> 5;
    const int wm = warp & 3;
    const int wn = warp >> 2;
    const long r0 = (long)blockIdx.y * 128;
    const int  c0 = blockIdx.x * 64;

    {
        const float4* ap = (const float4*)(A + r0 * 128);
#pragma unroll
        for (int i = 0; i < 16; i++) {
            int idx = tid + i * 256;
            int row = idx >> 5;
            int c4 = idx & 31;
            float4 v = ap[idx];
            unsigned* dst = As + row * AS_PITCH + c4 * 4;
            dst[0] = f2tf32(v.x); dst[1] = f2tf32(v.y);
            dst[2] = f2tf32(v.z); dst[3] = f2tf32(v.w);
        }
    }
    {
#pragma unroll
        for (int i = 0; i < 8; i++) {
            int idx = tid + i * 256;
            int row = idx >> 4;
            int c4 = idx & 15;
            float4 v = *(const float4*)(W + (long)row * CC + c0 + c4 * 4);
            unsigned* dst = Ws + row * WS_PITCH + c4 * 4;
            dst[0] = f2tf32(v.x); dst[1] = f2tf32(v.y);
            dst[2] = f2tf32(v.z); dst[3] = f2tf32(v.w);
        }
    }
    __syncthreads();

    const int gid = lane >> 2;
    const int tig = lane & 3;
    float c[2][4][4];
#pragma unroll
    for (int mt = 0; mt < 2; mt++)
#pragma unroll
        for (int nt = 0; nt < 4; nt++)
#pragma unroll
            for (int q = 0; q < 4; q++) c[mt][nt][q] = 0.f;

    const int arow = wm * 32 + gid;
    const int bcol = wn * 32 + gid;

#pragma unroll
    for (int k0 = 0; k0 < 128; k0 += 8) {
        unsigned a[2][4], b[4][2];
#pragma unroll
        for (int mt = 0; mt < 2; mt++) {
            const unsigned* ap = As + (arow + mt * 16) * AS_PITCH + k0 + tig;
            a[mt][0] = ap[0];
            a[mt][1] = ap[8 * AS_PITCH];
            a[mt][2] = ap[4];
            a[mt][3] = ap[8 * AS_PITCH + 4];
        }
#pragma unroll
        for (int nt = 0; nt < 4; nt++) {
            b[nt][0] = Ws[(k0 + tig) * WS_PITCH + bcol + nt * 8];
            b[nt][1] = Ws[(k0 + tig + 4) * WS_PITCH + bcol + nt * 8];
        }
#pragma unroll
        for (int mt = 0; mt < 2; mt++)
#pragma unroll
            for (int nt = 0; nt < 4; nt++)
                asm volatile(
                    "mma.sync.aligned.m16n8k8.row.col.f32.tf32.tf32.f32 "
                    "{%0,%1,%2,%3}, {%4,%5,%6,%7}, {%8,%9}, {%0,%1,%2,%3};"
                    : "+f"(c[mt][nt][0]), "+f"(c[mt][nt][1]),
                      "+f"(c[mt][nt][2]), "+f"(c[mt][nt][3])
                    : "r"(a[mt][0]), "r"(a[mt][1]), "r"(a[mt][2]), "r"(a[mt][3]),
                      "r"(b[nt][0]), "r"(b[nt][1]));
    }

#pragma unroll
    for (int mt = 0; mt < 2; mt++) {
        long r = r0 + wm * 32 + mt * 16 + gid;
#pragma unroll
        for (int nt = 0; nt < 4; nt++) {
            int col = c0 + wn * 32 + nt * 8 + 2 * tig;
            float2 bv = bias ? *(const float2*)(bias + col) : make_float2(0.f, 0.f);
            float2 v0 = make_float2(c[mt][nt][0] + bv.x, c[mt][nt][1] + bv.y);
            float2 v1 = make_float2(c[mt][nt][2] + bv.x, c[mt][nt][3] + bv.y);
            float* p0 = C + r * CC + col;
            float* p1 = C + (r + 8) * CC + col;
            if (accumulate) {
                float2 o0 = *(const float2*)p0;
                float2 o1 = *(const float2*)p1;
                v0.x += o0.x; v0.y += o0.y;
                v1.x += o1.x; v1.y += o1.y;
            }
            *(float2*)p0 = v0;
            *(float2*)p1 = v1;
        }
    }
}

// ---------------- CSR build: pair -> bridging edge list ---------------------
__global__ void csr_hist(const int* __restrict__ tri_pair, int T) {
    int i = blockIdx.x * blockDim.x + threadIdx.x;
    if (i < T) atomicAdd(&g_cnt[tri_pair[i]], 1);
}

// block-level exclusive scan, 1024 threads x 4 items = 4096 per block
__global__ void csr_scan_block(int P) {
    __shared__ int wsum[32];
    int tid = threadIdx.x;
    int base = blockIdx.x * 4096 + tid * 4;
    int v[4], s = 0;
#pragma unroll
    for (int q = 0; q < 4; q++) {
        v[q] = (base + q < P) ? g_cnt[base + q] : 0;
        s += v[q];
    }
    int lane = tid & 31, wid = tid >> 5;
    int x = s;
#pragma unroll
    for (int o = 1; o < 32; o <<= 1) {
        int y = __shfl_up_sync(0xffffffffu, x, o);
        if (lane >= o) x += y;
    }
    if (lane == 31) wsum[wid] = x;
    __syncthreads();
    if (wid == 0) {
        int w = wsum[lane];
#pragma unroll
        for (int o = 1; o < 32; o <<= 1) {
            int y = __shfl_up_sync(0xffffffffu, w, o);
            if (lane >= o) w += y;
        }
        wsum[lane] = w;
    }
    __syncthreads();
    int excl = x - s + (wid > 0 ? wsum[wid - 1] : 0);
    int run = excl;
#pragma unroll
    for (int q = 0; q < 4; q++) {
        if (base + q < P) g_off[base + q] = run;
        run += v[q];
    }
    if (tid == 0) g_partial[blockIdx.x] = 0;  // placeholder; real value below
    __syncthreads();
    if (tid == 1023) g_partial[blockIdx.x] = wsum[31];
}

__global__ void csr_scan_partials(int nb) {
    __shared__ int wsum[32];
    int tid = threadIdx.x;  // 1024
    int v = (tid < nb) ? g_partial[tid] : 0;
    int lane = tid & 31, wid = tid >> 5;
    int x = v;
#pragma unroll
    for (int o = 1; o < 32; o <<= 1) {
        int y = __shfl_up_sync(0xffffffffu, x, o);
        if (lane >= o) x += y;
    }
    if (lane == 31) wsum[wid] = x;
    __syncthreads();
    if (wid == 0) {
        int w = wsum[lane];
#pragma unroll
        for (int o = 1; o < 32; o <<= 1) {
            int y = __shfl_up_sync(0xffffffffu, w, o);
            if (lane >= o) w += y;
        }
        wsum[lane] = w;
    }
    __syncthreads();
    int excl = x - v + (wid > 0 ? wsum[wid - 1] : 0);
    if (tid < nb) g_partial[tid] = excl;
}

__global__ void csr_add_offsets(int P) {
    int i = blockIdx.x * blockDim.x + threadIdx.x;
    if (i < P) {
        int o = g_off[i] + g_partial[i >> 12];
        g_off[i] = o;
        g_head[i] = o;
    }
}

__global__ void csr_fill(const int* __restrict__ tri_pair,
                         const int* __restrict__ tri_edge, int T) {
    int i = blockIdx.x * blockDim.x + threadIdx.x;
    if (i < T) {
        int pos = atomicAdd(&g_head[tri_pair[i]], 1);
        g_csr[pos] = tri_edge[i];
    }
}

// ---------------- intra attention logits (warp per pair, CSR gather) --------
__global__ void intra_logits(const int* __restrict__ pair_src, const int* __restrict__ pair_tgt,
                             const float* __restrict__ pair_cnt,
                             const float4* __restrict__ bsi, const float4* __restrict__ bti,
                             const float4* __restrict__ bbi, const float4* __restrict__ ai,
                             int P) {
    int w = (int)(((long)blockIdx.x * blockDim.x + threadIdx.x) >> 5);
    int lane = threadIdx.x & 31;
    if (w >= P) return;
    int s = pair_src[w], t = pair_tgt[w];
    float inv = 1.0f / pair_cnt[w];
    int deg = g_cnt[w];
    int off = g_off[w];
    float4 acc0 = make_float4(0.f, 0.f, 0.f, 0.f);
    float4 acc1 = make_float4(0.f, 0.f, 0.f, 0.f);
    for (int j = 0; j < deg; j++) {
        int e = __ldg(&g_csr[off + j]);
        acc0 = f4add(acc0, g_edgeB[(long)e * 64 + lane]);
        acc1 = f4add(acc1, g_edgeB[(long)e * 64 + 32 + lane]);
    }
    float4 b0 = f4add(f4add(bsi[lane], bti[lane]), bbi[lane]);
    float4 b1 = f4add(f4add(bsi[32 + lane], bti[32 + lane]), bbi[32 + lane]);
    long sb = (long)s * 64 + lane, tb = (long)t * 64 + lane;
    float4 u0 = f4add(f4add(g_nodeS[sb], g_nodeT[tb]), f4fma(acc0, inv, b0));
    float4 u1 = f4add(f4add(g_nodeS[sb + 32], g_nodeT[tb + 32]), f4fma(acc1, inv, b1));
    float4 a0 = ai[lane], a1 = ai[32 + lane];
    float l0 = gelu_exact(u0.x) * a0.x + gelu_exact(u0.y) * a0.y +
               gelu_exact(u0.z) * a0.z + gelu_exact(u0.w) * a0.w;
    float l1 = gelu_exact(u1.x) * a1.x + gelu_exact(u1.y) * a1.y +
               gelu_exact(u1.z) * a1.z + gelu_exact(u1.w) * a1.w;
#pragma unroll
    for (int off2 = 16; off2; off2 >>= 1) {
        l0 += __shfl_down_sync(0xffffffffu, l0, off2);
        l1 += __shfl_down_sync(0xffffffffu, l1, off2);
    }
    if (lane == 0) {
        float e0 = expf(l0), e1 = expf(l1);
        g_exI[(long)w * 2] = e0;
        g_exI[(long)w * 2 + 1] = e1;
        atomicAdd(&g_denomI[t * 2], e0);
        atomicAdd(&g_denomI[t * 2 + 1], e1);
    }
}

// ---------------- intra message + softmax-scale + scatter (warp per pair) ---
__global__ void intra_msg(const int* __restrict__ pair_src, const int* __restrict__ pair_tgt,
                          const float* __restrict__ pair_cnt,
                          const float4* __restrict__ bmi, int P) {
    int w = (int)(((long)blockIdx.x * blockDim.x + threadIdx.x) >> 5);
    int lane = threadIdx.x & 31;
    if (w >= P) return;
    int s = pair_src[w], t = pair_tgt[w];
    float inv = 1.0f / pair_cnt[w];
    int deg = g_cnt[w];
    int off = g_off[w];
    float4 acc = make_float4(0.f, 0.f, 0.f, 0.f);
    for (int j = 0; j < deg; j++) {
        int e = __ldg(&g_csr[off + j]);
        acc = f4add(acc, g_edgeM[(long)e * 32 + lane]);
    }
    int h = lane >> 4;
    float sc = g_exI[(long)w * 2 + h] / g_denomI[t * 2 + h];
    float4 m = f4add(g_nodeM[(long)s * 32 + lane], f4fma(acc, inv, bmi[lane]));
    m = f4muls(m, sc);
    red4((float*)(g_accI + (long)t * 32 + lane), m);
}

// ---------------- inter attention logits (warp per incidence) ---------------
__global__ void inter_logits(const int* __restrict__ inc_edge, const int* __restrict__ inc_node,
                             const float4* __restrict__ bse, const float4* __restrict__ bte,
                             const float4* __restrict__ ae, int E) {
    int w = (int)(((long)blockIdx.x * blockDim.x + threadIdx.x) >> 5);
    int lane = threadIdx.x & 31;
    if (w >= E) return;
    int e = inc_edge[w], n = inc_node[w];
    float4 b0 = f4add(bse[lane], bte[lane]);
    float4 b1 = f4add(bse[32 + lane], bte[32 + lane]);
    long eb = (long)e * 64 + lane, nb = (long)n * 64 + lane;
    float4 u0 = f4add(f4add(g_edgeS[eb], g_nodeT2[nb]), b0);
    float4 u1 = f4add(f4add(g_edgeS[eb + 32], g_nodeT2[nb + 32]), b1);
    float4 a0 = ae[lane], a1 = ae[32 + lane];
    float l0 = gelu_exact(u0.x) * a0.x + gelu_exact(u0.y) * a0.y +
               gelu_exact(u0.z) * a0.z + gelu_exact(u0.w) * a0.w;
    float l1 = gelu_exact(u1.x) * a1.x + gelu_exact(u1.y) * a1.y +
               gelu_exact(u1.z) * a1.z + gelu_exact(u1.w) * a1.w;
#pragma unroll
    for (int off = 16; off; off >>= 1) {
        l0 += __shfl_down_sync(0xffffffffu, l0, off);
        l1 += __shfl_down_sync(0xffffffffu, l1, off);
    }
    if (lane == 0) {
        float e0 = expf(l0), e1 = expf(l1);
        g_exE[(long)w * 2] = e0;
        g_exE[(long)w * 2 + 1] = e1;
        atomicAdd(&g_denomE[n * 2], e0);
        atomicAdd(&g_denomE[n * 2 + 1], e1);
    }
}

// ---------------- inter message + scatter (warp per incidence) --------------
__global__ void inter_msg(const int* __restrict__ inc_edge, const int* __restrict__ inc_node,
                          const float4* __restrict__ bme, int E) {
    int w = (int)(((long)blockIdx.x * blockDim.x + threadIdx.x) >> 5);
    int lane = threadIdx.x & 31;
    if (w >= E) return;
    int e = inc_edge[w], n = inc_node[w];
    int h = lane >> 4;
    float sc = g_exE[(long)w * 2 + h] / g_denomE[n * 2 + h];
    float4 m = f4muls(f4add(g_edgeMe[(long)e * 32 + lane], bme[lane]), sc);
    red4((float*)(g_accE + (long)n * 32 + lane), m);
}

// ---------------- launch ----------------------------------------------------
extern "C" void kernel_launch(void* const* d_in, const int* in_sizes, int n_in,
                              void* d_out, int out_size) {
    const float* node_feat = (const float*)d_in[0];
    const float* edge_feat = (const float*)d_in[1];
    const int*   inc_node  = (const int*)d_in[2];
    const int*   inc_edge  = (const int*)d_in[3];
    const int*   pair_src  = (const int*)d_in[4];
    const int*   pair_tgt  = (const int*)d_in[5];
    const float* pair_cnt  = (const float*)d_in[6];
    const int*   tri_pair  = (const int*)d_in[7];
    const int*   tri_edge  = (const int*)d_in[8];
    const float* Wsi = (const float*)d_in[9];
    const float* bsi = (const float*)d_in[10];
    const float* Wti = (const float*)d_in[11];
    const float* bti = (const float*)d_in[12];
    const float* Wbi = (const float*)d_in[13];
    const float* bbi = (const float*)d_in[14];
    const float* ai  = (const float*)d_in[15];
    const float* Wmi = (const float*)d_in[16];
    const float* bmi = (const float*)d_in[17];
    const float* Woi = (const float*)d_in[18];
    const float* boi = (const float*)d_in[19];
    const float* Wse = (const float*)d_in[20];
    const float* bse = (const float*)d_in[21];
    const float* Wte = (const float*)d_in[22];
    const float* bte = (const float*)d_in[23];
    const float* ae  = (const float*)d_in[24];
    const float* Wme = (const float*)d_in[25];
    const float* bme = (const float*)d_in[26];
    const float* Woe = (const float*)d_in[27];
    const float* boe = (const float*)d_in[28];

    const int N = in_sizes[0] / 128;
    const int M = in_sizes[1] / 128;
    const int E = in_sizes[2];
    const int P = in_sizes[4];
    const int T = in_sizes[7];
    if (N > NMAX || M > MMAX || E > EMAX || P > PMAX || T > TMAX) return;

    float *pNodeS, *pNodeT, *pNodeT2, *pNodeM, *pEdgeB, *pEdgeS, *pEdgeM, *pEdgeMe;
    float *pAccI, *pAccE, *pDenI, *pDenE;
    int* pCnt;
    cudaGetSymbolAddress((void**)&pNodeS, g_nodeS);
    cudaGetSymbolAddress((void**)&pNodeT, g_nodeT);
    cudaGetSymbolAddress((void**)&pNodeT2, g_nodeT2);
    cudaGetSymbolAddress((void**)&pNodeM, g_nodeM);
    cudaGetSymbolAddress((void**)&pEdgeB, g_edgeB);
    cudaGetSymbolAddress((void**)&pEdgeS, g_edgeS);
    cudaGetSymbolAddress((void**)&pEdgeM, g_edgeM);
    cudaGetSymbolAddress((void**)&pEdgeMe, g_edgeMe);
    cudaGetSymbolAddress((void**)&pAccI, g_accI);
    cudaGetSymbolAddress((void**)&pAccE, g_accE);
    cudaGetSymbolAddress((void**)&pDenI, g_denomI);
    cudaGetSymbolAddress((void**)&pDenE, g_denomE);
    cudaGetSymbolAddress((void**)&pCnt, g_cnt);

    cudaFuncSetAttribute(gemm_tf32, cudaFuncAttributeMaxDynamicSharedMemorySize, GEMM_SMEM);

    float* out = (float*)d_out;

    // 1) zero the (small) atomically-accumulated scratch
    cudaMemsetAsync(pAccI, 0, (size_t)N * 128 * sizeof(float), 0);
    cudaMemsetAsync(pAccE, 0, (size_t)N * 128 * sizeof(float), 0);
    cudaMemsetAsync(pDenI, 0, (size_t)N * 2 * sizeof(float), 0);
    cudaMemsetAsync(pDenE, 0, (size_t)N * 2 * sizeof(float), 0);
    cudaMemsetAsync(pCnt, 0, (size_t)P * sizeof(int), 0);

    // 2) node / edge projection GEMMs (tf32 tensor cores, K = 128)
    gemm_tf32<<<dim3(4, N / 128), 256, GEMM_SMEM>>>(node_feat, Wsi, nullptr, pNodeS, 256, 0);
    gemm_tf32<<<dim3(4, N / 128), 256, GEMM_SMEM>>>(node_feat, Wti, nullptr, pNodeT, 256, 0);
    gemm_tf32<<<dim3(4, N / 128), 256, GEMM_SMEM>>>(node_feat, Wte, nullptr, pNodeT2, 256, 0);
    gemm_tf32<<<dim3(2, N / 128), 256, GEMM_SMEM>>>(node_feat, Wmi, nullptr, pNodeM, 128, 0);
    gemm_tf32<<<dim3(4, M / 128), 256, GEMM_SMEM>>>(edge_feat, Wbi, nullptr, pEdgeB, 256, 0);
    gemm_tf32<<<dim3(4, M / 128), 256, GEMM_SMEM>>>(edge_feat, Wse, nullptr, pEdgeS, 256, 0);
    gemm_tf32<<<dim3(2, M / 128), 256, GEMM_SMEM>>>(edge_feat, Wmi + 128 * 128, nullptr, pEdgeM, 128, 0);
    gemm_tf32<<<dim3(2, M / 128), 256, GEMM_SMEM>>>(edge_feat, Wme, nullptr, pEdgeMe, 128, 0);

    // 3) CSR build: pair -> bridging edges
    int nbScan = (P + 4095) / 4096;
    csr_hist<<<(T + 255) / 256, 256>>>(tri_pair, T);
    csr_scan_block<<<nbScan, 1024>>>(P);
    csr_scan_partials<<<1, 1024>>>(nbScan);
    csr_add_offsets<<<(P + 255) / 256, 256>>>(P);
    csr_fill<<<(T + 255) / 256, 256>>>(tri_pair, tri_edge, T);

    // 4) intra-rank attention (CSR bridge gather from L2-resident edge tables)
    int pb = (int)(((long)P * 32 + 255) / 256);
    intra_logits<<<pb, 256>>>(pair_src, pair_tgt, pair_cnt,
                              (const float4*)bsi, (const float4*)bti, (const float4*)bbi,
                              (const float4*)ai, P);
    intra_msg<<<pb, 256>>>(pair_src, pair_tgt, pair_cnt, (const float4*)bmi, P);

    // 5) inter-rank attention
    int eb = (int)(((long)E * 32 + 255) / 256);
    inter_logits<<<eb, 256>>>(inc_edge, inc_node,
                              (const float4*)bse, (const float4*)bte, (const float4*)ae, E);
    inter_msg<<<eb, 256>>>(inc_edge, inc_node, (const float4*)bme, E);

    // 6) output projections: out = accI @ Woi + boi + accE @ Woe + boe
    gemm_tf32<<<dim3(2, N / 128), 256, GEMM_SMEM>>>(pAccI, Woi, boi, out, 128, 0);
    gemm_tf32<<<dim3(2, N / 128), 256, GEMM_SMEM>>>(pAccE, Woe, boe, out, 128, 1);
}

// round 4
// speedup vs baseline: 1.9339x; 1.0517x over previous
#include <cuda_runtime.h>
#include <cuda_fp16.h>

// ---------------- problem constants ----------------
// N=32768, M=8192, D=128, H=128, NH=2 -> hidden 256, HD=64
#define NMAX 32768
#define MMAX 8192
#define EMAX 49152
#define TMAX 294912
#define PMAX (TMAX + NMAX)

// node table cols: [0:256) S(+bias) | [256:512) T | [512:768) T2(+bias) | [768:896) M(+bmi)
#define NCC 896
// edge table cols: [0:256) B | [256:512) S | [512:640) M | [640:768) Me(+bme)
#define ECC 768

// ---------------- scratch ----------------
__device__ __half g_node[(size_t)NMAX * NCC];
__device__ __half g_edge[(size_t)MMAX * ECC];
__device__ float  g_accO[(size_t)NMAX * 256];   // [N][256]: intra 0-127, inter 128-255
__device__ float  g_Wn[128 * NCC];
__device__ float  g_We[128 * ECC];
__device__ float  g_Wo[256 * 128];
__device__ float  g_bn[NCC];
__device__ float  g_be[ECC];
__device__ float  g_bo[128];
__device__ float  g_exI[PMAX * 2];
__device__ float  g_exE[EMAX * 2];
__device__ float  g_denomI[NMAX * 2];
__device__ float  g_denomE[NMAX * 2];
__device__ int    g_cnt[PMAX];
__device__ int    g_off[PMAX];
__device__ int    g_head[PMAX];
__device__ int    g_csr[TMAX];
__device__ int    g_partial[1024];

// ---------------- helpers ----------------
__device__ __forceinline__ float gelu_exact(float x) {
    return 0.5f * x * (1.0f + erff(x * 0.70710678118654752f));
}
__device__ __forceinline__ void red4(float* addr, float a, float b, float c, float d) {
    asm volatile("red.global.add.v4.f32 [%0], {%1,%2,%3,%4};"
                 :: "l"(addr), "f"(a), "f"(b), "f"(c), "f"(d) : "memory");
}
__device__ __forceinline__ unsigned f2tf32(float x) {
    unsigned r;
    asm("cvt.rna.tf32.f32 %0, %1;" : "=r"(r) : "f"(x));
    return r;
}
__device__ __forceinline__ void load_h8(const __half* p, float* f) {
    uint4 r = *(const uint4*)p;
    float2 v;
    v = __half22float2(*(__half2*)&r.x); f[0] = v.x; f[1] = v.y;
    v = __half22float2(*(__half2*)&r.y); f[2] = v.x; f[3] = v.y;
    v = __half22float2(*(__half2*)&r.z); f[4] = v.x; f[5] = v.y;
    v = __half22float2(*(__half2*)&r.w); f[6] = v.x; f[7] = v.y;
}
__device__ __forceinline__ void load_h4(const __half* p, float* f) {
    uint2 r = *(const uint2*)p;
    float2 v;
    v = __half22float2(*(__half2*)&r.x); f[0] = v.x; f[1] = v.y;
    v = __half22float2(*(__half2*)&r.y); f[2] = v.x; f[3] = v.y;
}

// ---------------- weight/bias packing ----------------
__global__ void pack_weights(const float* __restrict__ Wsi, const float* __restrict__ Wti,
                             const float* __restrict__ Wte, const float* __restrict__ Wmi,
                             const float* __restrict__ Wbi, const float* __restrict__ Wse,
                             const float* __restrict__ Wme,
                             const float* __restrict__ Woi, const float* __restrict__ Woe,
                             const float* __restrict__ bsi, const float* __restrict__ bti,
                             const float* __restrict__ bbi, const float* __restrict__ bse,
                             const float* __restrict__ bte, const float* __restrict__ bmi,
                             const float* __restrict__ bme, const float* __restrict__ boi,
                             const float* __restrict__ boe) {
    int i = blockIdx.x * blockDim.x + threadIdx.x;
    if (i < 128 * NCC) {
        int r = i / NCC, c = i % NCC;
        float v;
        if (c < 256) v = Wsi[r * 256 + c];
        else if (c < 512) v = Wti[r * 256 + (c - 256)];
        else if (c < 768) v = Wte[r * 256 + (c - 512)];
        else v = Wmi[r * 128 + (c - 768)];            // Wmi top half (rows 0-127)
        g_Wn[i] = v;
    }
    if (i < 128 * ECC) {
        int r = i / ECC, c = i % ECC;
        float v;
        if (c < 256) v = Wbi[r * 256 + c];
        else if (c < 512) v = Wse[r * 256 + (c - 256)];
        else if (c < 640) v = Wmi[(128 + r) * 128 + (c - 512)];  // Wmi bottom half
        else v = Wme[r * 128 + (c - 640)];
        g_We[i] = v;
    }
    if (i < 256 * 128) {
        int r = i / 128, c = i % 128;
        g_Wo[i] = (r < 128) ? Woi[r * 128 + c] : Woe[(r - 128) * 128 + c];
    }
    if (i < NCC) {
        float v;
        if (i < 256) v = bsi[i] + bti[i] + bbi[i];
        else if (i < 512) v = 0.f;
        else if (i < 768) v = bse[i - 512] + bte[i - 512];
        else v = bmi[i - 768];
        g_bn[i] = v;
    }
    if (i < ECC) g_be[i] = (i >= 640) ? bme[i - 640] : 0.f;
    if (i < 128) g_bo[i] = boi[i] + boe[i];
}

// ---------------- tf32 tensor-core GEMM, CTA tile 128x128, K-looped ---------
#define AS_PITCH 132
#define WS_PITCH 136
#define GEMM_SMEM ((128 * AS_PITCH + 128 * WS_PITCH) * 4)

template <bool HALF_OUT>
__global__ void gemm_tf32_t(const float* __restrict__ A, const float* __restrict__ W,
                            const float* __restrict__ bias, void* __restrict__ Cv,
                            int KK, int CC) {
    extern __shared__ unsigned sh[];
    unsigned* As = sh;                      // [128][AS_PITCH]
    unsigned* Ws = sh + 128 * AS_PITCH;     // [128][WS_PITCH]
    const int tid = threadIdx.x;
    const int lane = tid & 31;
    const int warp = tid >> 5;
    const int wm = warp & 3;                // 4 warps x 32 rows
    const int wn = warp >> 2;               // 2 warps x 64 cols
    const long r0 = (long)blockIdx.y * 128;
    const int  c0 = blockIdx.x * 128;
    const int gid = lane >> 2;
    const int tig = lane & 3;

    float c[2][8][4];
#pragma unroll
    for (int mt = 0; mt < 2; mt++)
#pragma unroll
        for (int nt = 0; nt < 8; nt++)
#pragma unroll
            for (int q = 0; q < 4; q++) c[mt][nt][q] = 0.f;

    for (int kb = 0; kb < KK; kb += 128) {
        if (kb) __syncthreads();
        // stage A chunk [128][128]
#pragma unroll
        for (int i = 0; i < 16; i++) {
            int idx = tid + i * 256;
            int row = idx >> 5;
            int c4 = idx & 31;
            float4 v = *(const float4*)(A + (r0 + row) * KK + kb + c4 * 4);
            unsigned* dst = As + row * AS_PITCH + c4 * 4;
            dst[0] = f2tf32(v.x); dst[1] = f2tf32(v.y);
            dst[2] = f2tf32(v.z); dst[3] = f2tf32(v.w);
        }
        // stage W chunk [128][128]
#pragma unroll
        for (int i = 0; i < 16; i++) {
            int idx = tid + i * 256;
            int row = idx >> 5;
            int c4 = idx & 31;
            float4 v = *(const float4*)(W + (long)(kb + row) * CC + c0 + c4 * 4);
            unsigned* dst = Ws + row * WS_PITCH + c4 * 4;
            dst[0] = f2tf32(v.x); dst[1] = f2tf32(v.y);
            dst[2] = f2tf32(v.z); dst[3] = f2tf32(v.w);
        }
        __syncthreads();

        const int arow = wm * 32 + gid;
        const int bcol = wn * 64 + gid;
#pragma unroll
        for (int k0 = 0; k0 < 128; k0 += 8) {
            unsigned a[2][4], b[8][2];
#pragma unroll
            for (int mt = 0; mt < 2; mt++) {
                const unsigned* ap = As + (arow + mt * 16) * AS_PITCH + k0 + tig;
                a[mt][0] = ap[0];
                a[mt][1] = ap[8 * AS_PITCH];
                a[mt][2] = ap[4];
                a[mt][3] = ap[8 * AS_PITCH + 4];
            }
#pragma unroll
            for (int nt = 0; nt < 8; nt++) {
                b[nt][0] = Ws[(k0 + tig) * WS_PITCH + bcol + nt * 8];
                b[nt][1] = Ws[(k0 + tig + 4) * WS_PITCH + bcol + nt * 8];
            }
#pragma unroll
            for (int mt = 0; mt < 2; mt++)
#pragma unroll
                for (int nt = 0; nt < 8; nt++)
                    asm volatile(
                        "mma.sync.aligned.m16n8k8.row.col.f32.tf32.tf32.f32 "
                        "{%0,%1,%2,%3}, {%4,%5,%6,%7}, {%8,%9}, {%0,%1,%2,%3};"
                        : "+f"(c[mt][nt][0]), "+f"(c[mt][nt][1]),
                          "+f"(c[mt][nt][2]), "+f"(c[mt][nt][3])
                        : "r"(a[mt][0]), "r"(a[mt][1]), "r"(a[mt][2]), "r"(a[mt][3]),
                          "r"(b[nt][0]), "r"(b[nt][1]));
        }
    }

#pragma unroll
    for (int mt = 0; mt < 2; mt++) {
        long r = r0 + wm * 32 + mt * 16 + gid;
#pragma unroll
        for (int nt = 0; nt < 8; nt++) {
            int col = c0 + wn * 64 + nt * 8 + 2 * tig;
            float2 bv = bias ? *(const float2*)(bias + col) : make_float2(0.f, 0.f);
            float x0 = c[mt][nt][0] + bv.x, y0 = c[mt][nt][1] + bv.y;
            float x1 = c[mt][nt][2] + bv.x, y1 = c[mt][nt][3] + bv.y;
            if (HALF_OUT) {
                __half* C = (__half*)Cv;
                *(__half2*)(C + r * CC + col) = __floats2half2_rn(x0, y0);
                *(__half2*)(C + (r + 8) * CC + col) = __floats2half2_rn(x1, y1);
            } else {
                float* C = (float*)Cv;
                *(float2*)(C + r * CC + col) = make_float2(x0, y0);
                *(float2*)(C + (r + 8) * CC + col) = make_float2(x1, y1);
            }
        }
    }
}

// ---------------- CSR build ----------------
__global__ void csr_hist(const int* __restrict__ tri_pair, int T) {
    int i = blockIdx.x * blockDim.x + threadIdx.x;
    if (i < T) atomicAdd(&g_cnt[tri_pair[i]], 1);
}

__global__ void csr_scan_block(int P) {
    __shared__ int wsum[32];
    int tid = threadIdx.x;
    int base = blockIdx.x * 4096 + tid * 4;
    int v[4], s = 0;
#pragma unroll
    for (int q = 0; q < 4; q++) {
        v[q] = (base + q < P) ? g_cnt[base + q] : 0;
        s += v[q];
    }
    int lane = tid & 31, wid = tid >> 5;
    int x = s;
#pragma unroll
    for (int o = 1; o < 32; o <<= 1) {
        int y = __shfl_up_sync(0xffffffffu, x, o);
        if (lane >= o) x += y;
    }
    if (lane == 31) wsum[wid] = x;
    __syncthreads();
    if (wid == 0) {
        int w = wsum[lane];
#pragma unroll
        for (int o = 1; o < 32; o <<= 1) {
            int y = __shfl_up_sync(0xffffffffu, w, o);
            if (lane >= o) w += y;
        }
        wsum[lane] = w;
    }
    __syncthreads();
    int excl = x - s + (wid > 0 ? wsum[wid - 1] : 0);
    int run = excl;
#pragma unroll
    for (int q = 0; q < 4; q++) {
        if (base + q < P) g_off[base + q] = run;
        run += v[q];
    }
    if (tid == 1023) g_partial[blockIdx.x] = wsum[31];
}

__global__ void csr_scan_partials(int nb) {
    __shared__ int wsum[32];
    int tid = threadIdx.x;
    int v = (tid < nb) ? g_partial[tid] : 0;
    int lane = tid & 31, wid = tid >> 5;
    int x = v;
#pragma unroll
    for (int o = 1; o < 32; o <<= 1) {
        int y = __shfl_up_sync(0xffffffffu, x, o);
        if (lane >= o) x += y;
    }
    if (lane == 31) wsum[wid] = x;
    __syncthreads();
    if (wid == 0) {
        int w = wsum[lane];
#pragma unroll
        for (int o = 1; o < 32; o <<= 1) {
            int y = __shfl_up_sync(0xffffffffu, w, o);
            if (lane >= o) w += y;
        }
        wsum[lane] = w;
    }
    __syncthreads();
    int excl = x - v + (wid > 0 ? wsum[wid - 1] : 0);
    if (tid < nb) g_partial[tid] = excl;
}

__global__ void csr_add_offsets(int P) {
    int i = blockIdx.x * blockDim.x + threadIdx.x;
    if (i < P) {
        int o = g_off[i] + g_partial[i >> 12];
        g_off[i] = o;
        g_head[i] = o;
    }
}

__global__ void csr_fill(const int* __restrict__ tri_pair,
                         const int* __restrict__ tri_edge, int T) {
    int i = blockIdx.x * blockDim.x + threadIdx.x;
    if (i < T) {
        int pos = atomicAdd(&g_head[tri_pair[i]], 1);
        g_csr[pos] = tri_edge[i];
    }
}

// ---------------- intra attention logits (warp per pair) --------------------
__global__ void intra_logits(const int* __restrict__ pair_src, const int* __restrict__ pair_tgt,
                             const float* __restrict__ pair_cnt,
                             const float* __restrict__ ai, int P) {
    int w = (int)(((long)blockIdx.x * blockDim.x + threadIdx.x) >> 5);
    int lane = threadIdx.x & 31;
    if (w >= P) return;
    int s = pair_src[w], t = pair_tgt[w];
    float inv = 1.0f / pair_cnt[w];
    int deg = g_cnt[w];
    int off = g_off[w];

    float u[8], tv[8];
    load_h8(g_node + (size_t)s * NCC + lane * 8, u);            // S block (+bias)
    load_h8(g_node + (size_t)t * NCC + 256 + lane * 8, tv);     // T block
    float ab[8] = {0.f, 0.f, 0.f, 0.f, 0.f, 0.f, 0.f, 0.f};
    for (int j = 0; j < deg; j++) {
        int e = __ldg(&g_csr[off + j]);
        float bv[8];
        load_h8(g_edge + (size_t)e * ECC + lane * 8, bv);       // B block
#pragma unroll
        for (int q = 0; q < 8; q++) ab[q] += bv[q];
    }
    float4 a0 = *(const float4*)(ai + lane * 8);
    float4 a1 = *(const float4*)(ai + lane * 8 + 4);
    float av[8] = {a0.x, a0.y, a0.z, a0.w, a1.x, a1.y, a1.z, a1.w};
    float partial = 0.f;
#pragma unroll
    for (int q = 0; q < 8; q++)
        partial += gelu_exact(u[q] + tv[q] + ab[q] * inv) * av[q];
    // lanes 0-15 -> head 0, lanes 16-31 -> head 1
#pragma unroll
    for (int o = 8; o; o >>= 1) partial += __shfl_down_sync(0xffffffffu, partial, o);
    float l1 = __shfl_sync(0xffffffffu, partial, 16);
    if (lane == 0) {
        float e0 = expf(partial), e1 = expf(l1);
        g_exI[(long)w * 2] = e0;
        g_exI[(long)w * 2 + 1] = e1;
        atomicAdd(&g_denomI[t * 2], e0);
        atomicAdd(&g_denomI[t * 2 + 1], e1);
    }
}

// ---------------- intra message + scatter (warp per pair) -------------------
__global__ void intra_msg(const int* __restrict__ pair_src, const int* __restrict__ pair_tgt,
                          const float* __restrict__ pair_cnt, int P) {
    int w = (int)(((long)blockIdx.x * blockDim.x + threadIdx.x) >> 5);
    int lane = threadIdx.x & 31;
    if (w >= P) return;
    int s = pair_src[w], t = pair_tgt[w];
    float inv = 1.0f / pair_cnt[w];
    int deg = g_cnt[w];
    int off = g_off[w];

    float m[4];
    load_h4(g_node + (size_t)s * NCC + 768 + lane * 4, m);      // M block (+bmi)
    float am[4] = {0.f, 0.f, 0.f, 0.f};
    for (int j = 0; j < deg; j++) {
        int e = __ldg(&g_csr[off + j]);
        float mv[4];
        load_h4(g_edge + (size_t)e * ECC + 512 + lane * 4, mv); // M block
#pragma unroll
        for (int q = 0; q < 4; q++) am[q] += mv[q];
    }
    int h = lane >> 4;
    float sc = g_exI[(long)w * 2 + h] / g_denomI[t * 2 + h];
    red4(g_accO + (size_t)t * 256 + lane * 4,
         (m[0] + am[0] * inv) * sc, (m[1] + am[1] * inv) * sc,
         (m[2] + am[2] * inv) * sc, (m[3] + am[3] * inv) * sc);
}

// ---------------- inter attention logits (warp per incidence) ---------------
__global__ void inter_logits(const int* __restrict__ inc_edge, const int* __restrict__ inc_node,
                             const float* __restrict__ ae, int E) {
    int w = (int)(((long)blockIdx.x * blockDim.x + threadIdx.x) >> 5);
    int lane = threadIdx.x & 31;
    if (w >= E) return;
    int e = inc_edge[w], n = inc_node[w];
    float u[8], tv[8];
    load_h8(g_edge + (size_t)e * ECC + 256 + lane * 8, u);      // S(e) block
    load_h8(g_node + (size_t)n * NCC + 512 + lane * 8, tv);     // T2 block (+bias)
    float4 a0 = *(const float4*)(ae + lane * 8);
    float4 a1 = *(const float4*)(ae + lane * 8 + 4);
    float av[8] = {a0.x, a0.y, a0.z, a0.w, a1.x, a1.y, a1.z, a1.w};
    float partial = 0.f;
#pragma unroll
    for (int q = 0; q < 8; q++)
        partial += gelu_exact(u[q] + tv[q]) * av[q];
#pragma unroll
    for (int o = 8; o; o >>= 1) partial += __shfl_down_sync(0xffffffffu, partial, o);
    float l1 = __shfl_sync(0xffffffffu, partial, 16);
    if (lane == 0) {
        float e0 = expf(partial), e1 = expf(l1);
        g_exE[(long)w * 2] = e0;
        g_exE[(long)w * 2 + 1] = e1;
        atomicAdd(&g_denomE[n * 2], e0);
        atomicAdd(&g_denomE[n * 2 + 1], e1);
    }
}

// ---------------- inter message + scatter (warp per incidence) --------------
__global__ void inter_msg(const int* __restrict__ inc_edge, const int* __restrict__ inc_node,
                          int E) {
    int w = (int)(((long)blockIdx.x * blockDim.x + threadIdx.x) >> 5);
    int lane = threadIdx.x & 31;
    if (w >= E) return;
    int e = inc_edge[w], n = inc_node[w];
    int h = lane >> 4;
    float sc = g_exE[(long)w * 2 + h] / g_denomE[n * 2 + h];
    float m[4];
    load_h4(g_edge + (size_t)e * ECC + 640 + lane * 4, m);      // Me block (+bme)
    red4(g_accO + (size_t)n * 256 + 128 + lane * 4,
         m[0] * sc, m[1] * sc, m[2] * sc, m[3] * sc);
}

// ---------------- launch ----------------
extern "C" void kernel_launch(void* const* d_in, const int* in_sizes, int n_in,
                              void* d_out, int out_size) {
    const float* node_feat = (const float*)d_in[0];
    const float* edge_feat = (const float*)d_in[1];
    const int*   inc_node  = (const int*)d_in[2];
    const int*   inc_edge  = (const int*)d_in[3];
    const int*   pair_src  = (const int*)d_in[4];
    const int*   pair_tgt  = (const int*)d_in[5];
    const float* pair_cnt  = (const float*)d_in[6];
    const int*   tri_pair  = (const int*)d_in[7];
    const int*   tri_edge  = (const int*)d_in[8];
    const float* Wsi = (const float*)d_in[9];
    const float* bsi = (const float*)d_in[10];
    const float* Wti = (const float*)d_in[11];
    const float* bti = (const float*)d_in[12];
    const float* Wbi = (const float*)d_in[13];
    const float* bbi = (const float*)d_in[14];
    const float* ai  = (const float*)d_in[15];
    const float* Wmi = (const float*)d_in[16];
    const float* bmi = (const float*)d_in[17];
    const float* Woi = (const float*)d_in[18];
    const float* boi = (const float*)d_in[19];
    const float* Wse = (const float*)d_in[20];
    const float* bse = (const float*)d_in[21];
    const float* Wte = (const float*)d_in[22];
    const float* bte = (const float*)d_in[23];
    const float* ae  = (const float*)d_in[24];
    const float* Wme = (const float*)d_in[25];
    const float* bme = (const float*)d_in[26];
    const float* Woe = (const float*)d_in[27];
    const float* boe = (const float*)d_in[28];

    const int N = in_sizes[0] / 128;
    const int M = in_sizes[1] / 128;
    const int E = in_sizes[2];
    const int P = in_sizes[4];
    const int T = in_sizes[7];
    if (N > NMAX || M > MMAX || E > EMAX || P > PMAX || T > TMAX) return;

    void *pNode, *pEdge, *pAccO, *pWn, *pWe, *pWo, *pBn, *pBe, *pBo, *pDenI, *pDenE, *pCnt;
    cudaGetSymbolAddress(&pNode, g_node);
    cudaGetSymbolAddress(&pEdge, g_edge);
    cudaGetSymbolAddress(&pAccO, g_accO);
    cudaGetSymbolAddress(&pWn, g_Wn);
    cudaGetSymbolAddress(&pWe, g_We);
    cudaGetSymbolAddress(&pWo, g_Wo);
    cudaGetSymbolAddress(&pBn, g_bn);
    cudaGetSymbolAddress(&pBe, g_be);
    cudaGetSymbolAddress(&pBo, g_bo);
    cudaGetSymbolAddress(&pDenI, g_denomI);
    cudaGetSymbolAddress(&pDenE, g_denomE);
    cudaGetSymbolAddress(&pCnt, g_cnt);

    cudaFuncSetAttribute(gemm_tf32_t<true>, cudaFuncAttributeMaxDynamicSharedMemorySize, GEMM_SMEM);
    cudaFuncSetAttribute(gemm_tf32_t<false>, cudaFuncAttributeMaxDynamicSharedMemorySize, GEMM_SMEM);

    float* out = (float*)d_out;

    // 1) zero accumulators + CSR counters
    cudaMemsetAsync(pAccO, 0, (size_t)N * 256 * sizeof(float), 0);
    cudaMemsetAsync(pDenI, 0, (size_t)N * 2 * sizeof(float), 0);
    cudaMemsetAsync(pDenE, 0, (size_t)N * 2 * sizeof(float), 0);
    cudaMemsetAsync(pCnt, 0, (size_t)P * sizeof(int), 0);

    // 2) pack weights / biases
    pack_weights<<<(128 * NCC + 255) / 256, 256>>>(Wsi, Wti, Wte, Wmi, Wbi, Wse, Wme, Woi, Woe,
                                                   bsi, bti, bbi, bse, bte, bmi, bme, boi, boe);

    // 3) projection GEMMs -> combined fp16 tables (biases baked in)
    gemm_tf32_t<true><<<dim3(NCC / 128, N / 128), 256, GEMM_SMEM>>>(
        node_feat, (const float*)pWn, (const float*)pBn, pNode, 128, NCC);
    gemm_tf32_t<true><<<dim3(ECC / 128, M / 128), 256, GEMM_SMEM>>>(
        edge_feat, (const float*)pWe, (const float*)pBe, pEdge, 128, ECC);

    // 4) CSR build: pair -> bridging edges
    int nbScan = (P + 4095) / 4096;
    csr_hist<<<(T + 255) / 256, 256>>>(tri_pair, T);
    csr_scan_block<<<nbScan, 1024>>>(P);
    csr_scan_partials<<<1, 1024>>>(nbScan);
    csr_add_offsets<<<(P + 255) / 256, 256>>>(P);
    csr_fill<<<(T + 255) / 256, 256>>>(tri_pair, tri_edge, T);

    // 5) intra-rank attention
    int pb = (int)(((long)P * 32 + 255) / 256);
    intra_logits<<<pb, 256>>>(pair_src, pair_tgt, pair_cnt, ai, P);
    intra_msg<<<pb, 256>>>(pair_src, pair_tgt, pair_cnt, P);

    // 6) inter-rank attention
    int eb = (int)(((long)E * 32 + 255) / 256);
    inter_logits<<<eb, 256>>>(inc_edge, inc_node, ae, E);
    inter_msg<<<eb, 256>>>(inc_edge, inc_node, E);

    // 7) fused output projection: out = [accI|accE] @ [Woi;Woe] + (boi+boe)
    gemm_tf32_t<false><<<dim3(1, N / 128), 256, GEMM_SMEM>>>(
        (const float*)pAccO, (const float*)pWo, (const float*)pBo, out, 256, 128);
}